// round 8
// baseline (speedup 1.0000x reference)
#include <cuda_runtime.h>
#include <cuda_bf16.h>
#include <cstdint>
#include <math.h>

#define DI __device__ __forceinline__

static constexpr int B_DIM = 8;
static constexpr int SEQ   = 1024;
static constexpr int CH    = 768;
static constexpr int NH    = 12;
static constexpr int HD    = 64;
static constexpr int HID   = 3072;
static constexpr int ROWS  = B_DIM * SEQ;   // 8192
static constexpr int BH    = B_DIM * NH;    // 96

// fp8 scaling: activations x8, weights x32, epilogue folds 1/256
static constexpr float ACT_S  = 8.f;
static constexpr float W_S    = 32.f;
static constexpr float INV_S  = 1.f / 256.f;

// ---------------- scratch: device globals (no runtime allocation) ------------
__device__ uint8_t g_h1[ROWS * CH];                 // fp8 LN1 out (x8)
__device__ uint8_t g_h2[ROWS * CH];                 // fp8 LN2 out (x8)
__device__ uint8_t g_wqkvT[3 * CH * CH];            // fp8 weights (x32)
__device__ uint8_t g_wprojT[CH * CH];
__device__ uint8_t g_w1T[HID * CH];
__device__ uint8_t g_w2T[CH * HID];
__device__ __nv_bfloat16 g_q[BH * SEQ * HD];        // bf16 (flash attn inputs)
__device__ __nv_bfloat16 g_k[BH * SEQ * HD];
__device__ __nv_bfloat16 g_v[BH * SEQ * HD];
__device__ uint8_t g_attn[ROWS * CH];               // fp8 attn out (x8)
__device__ float   g_x1[ROWS * CH];
__device__ uint8_t g_mid[(size_t)ROWS * HID];       // fp8 gelu out (x8)

// ---------------- PTX helpers -------------------------------------------------

DI void cp16(uint32_t s, const void* g) {
    asm volatile("cp.async.cg.shared.global [%0], [%1], 16;\n" :: "r"(s), "l"(g));
}
DI void cp_commit() { asm volatile("cp.async.commit_group;\n"); }
template <int N> DI void cp_wait() { asm volatile("cp.async.wait_group %0;\n" :: "n"(N)); }

DI void ldsm_x4(uint32_t* r, uint32_t addr) {
    asm volatile("ldmatrix.sync.aligned.m8n8.x4.shared.b16 {%0,%1,%2,%3}, [%4];\n"
                 : "=r"(r[0]), "=r"(r[1]), "=r"(r[2]), "=r"(r[3]) : "r"(addr));
}
DI void ldsm_x4_t(uint32_t* r, uint32_t addr) {
    asm volatile("ldmatrix.sync.aligned.m8n8.x4.trans.shared.b16 {%0,%1,%2,%3}, [%4];\n"
                 : "=r"(r[0]), "=r"(r[1]), "=r"(r[2]), "=r"(r[3]) : "r"(addr));
}

DI void mma_bf16(float* c, const uint32_t* a, uint32_t b0, uint32_t b1) {
    asm volatile(
        "mma.sync.aligned.m16n8k16.row.col.f32.bf16.bf16.f32 "
        "{%0,%1,%2,%3}, {%4,%5,%6,%7}, {%8,%9}, {%0,%1,%2,%3};\n"
        : "+f"(c[0]), "+f"(c[1]), "+f"(c[2]), "+f"(c[3])
        : "r"(a[0]), "r"(a[1]), "r"(a[2]), "r"(a[3]), "r"(b0), "r"(b1));
}

// fp8 e4m3 mma: m16n8k32, fragments are byte-identical to m16n8k16-b16 with
// each 16-bit slot holding 2 consecutive-k fp8 values.
DI void mma_fp8(float* c, const uint32_t* a, uint32_t b0, uint32_t b1) {
    asm volatile(
        "mma.sync.aligned.m16n8k32.row.col.f32.e4m3.e4m3.f32 "
        "{%0,%1,%2,%3}, {%4,%5,%6,%7}, {%8,%9}, {%0,%1,%2,%3};\n"
        : "+f"(c[0]), "+f"(c[1]), "+f"(c[2]), "+f"(c[3])
        : "r"(a[0]), "r"(a[1]), "r"(a[2]), "r"(a[3]), "r"(b0), "r"(b1));
}

DI uint32_t packbf(float lo, float hi) {
    __nv_bfloat162 t = __float22bfloat162_rn(make_float2(lo, hi));
    return *reinterpret_cast<uint32_t*>(&t);
}
DI uint16_t fp8x2(float lo, float hi) {
    uint16_t t;
    asm("cvt.rn.satfinite.e4m3x2.f32 %0, %1, %2;" : "=h"(t) : "f"(hi), "f"(lo));
    return t;
}
DI uint8_t fp8_1(float v) { return (uint8_t)fp8x2(v, 0.f); }

// ---------------- small helper kernels ---------------------------------------

// out[n][k] = fp8(in[k][n] * W_S)
__global__ void transpose_fp8(const float* __restrict__ in,
                              uint8_t* __restrict__ out, int K, int Nc) {
    __shared__ float tile[32][33];
    int kb = blockIdx.y * 32, nb = blockIdx.x * 32;
    int tx = threadIdx.x, ty = threadIdx.y;   // block (32, 8)
#pragma unroll
    for (int i = 0; i < 4; i++)
        tile[ty + i * 8][tx] = in[(size_t)(kb + ty + i * 8) * Nc + nb + tx];
    __syncthreads();
#pragma unroll
    for (int i = 0; i < 4; i++)
        out[(size_t)(nb + ty + i * 8) * K + kb + tx] =
            fp8_1(tile[tx][ty + i * 8] * W_S);
}

// LayerNorm, fp32 in -> fp8 out (x ACT_S)
__global__ void ln_kernel(const float* __restrict__ x, const float* __restrict__ g,
                          const float* __restrict__ b, uint8_t* __restrict__ out) {
    int row = blockIdx.x;
    const float* xr = x + (size_t)row * CH;
    int t = threadIdx.x;
    float v0 = xr[t], v1 = xr[t + 256], v2 = xr[t + 512];
    float s  = v0 + v1 + v2;
    float s2 = v0 * v0 + v1 * v1 + v2 * v2;
#pragma unroll
    for (int o = 16; o; o >>= 1) {
        s  += __shfl_xor_sync(0xffffffffu, s,  o);
        s2 += __shfl_xor_sync(0xffffffffu, s2, o);
    }
    __shared__ float sh[16];
    int w = t >> 5, l = t & 31;
    if (l == 0) { sh[w] = s; sh[w + 8] = s2; }
    __syncthreads();
    float ts = 0.f, ts2 = 0.f;
#pragma unroll
    for (int i = 0; i < 8; i++) { ts += sh[i]; ts2 += sh[i + 8]; }
    float mu  = ts * (1.f / CH);
    float var = ts2 * (1.f / CH) - mu * mu;
    float inv = rsqrtf(var + 1e-5f);
    uint8_t* orow = out + (size_t)row * CH;
    orow[t]       = fp8_1(((v0 - mu) * inv * g[t]       + b[t])       * ACT_S);
    orow[t + 256] = fp8_1(((v1 - mu) * inv * g[t + 256] + b[t + 256]) * ACT_S);
    orow[t + 512] = fp8_1(((v2 - mu) * inv * g[t + 512] + b[t + 512]) * ACT_S);
}

// ---------------- fused flash attention (bf16; output now fp8) ---------------

__global__ void __launch_bounds__(256)
flash_attn(const __nv_bfloat16* __restrict__ Q, const __nv_bfloat16* __restrict__ K,
           const __nv_bfloat16* __restrict__ V, const float* __restrict__ temp,
           const float* __restrict__ lw, uint8_t* __restrict__ attn) {
    constexpr int ITERS = SEQ / 64;           // 16
    __shared__ __align__(16) uint8_t smem[49152];
    uint32_t sQ = (uint32_t)__cvta_generic_to_shared(smem);
    uint32_t sK = sQ + 16384;
    uint32_t sV = sK + 16384;

    int bh = blockIdx.y;
    int b = bh / NH, h = bh % NH;
    int qbase = blockIdx.x * 128;
    const __nv_bfloat16* qb = Q + ((size_t)bh * SEQ + qbase) * HD;
    const __nv_bfloat16* kb = K + (size_t)bh * SEQ * HD;
    const __nv_bfloat16* vb = V + (size_t)bh * SEQ * HD;

    int tid = threadIdx.x, lane = tid & 31, w = tid >> 5;
    int g = lane >> 2, ct = lane & 3;

    auto issue_kv = [&](int t, int stage) {
#pragma unroll
        for (int i = 0; i < 2; i++) {
            int idx = tid + i * 256;
            int r = idx >> 3, c = idx & 7;
            uint32_t sw = (uint32_t)((c ^ (r & 7)) << 4);
            cp16(sK + stage * 8192 + r * 128 + sw, kb + (size_t)(t * 64 + r) * HD + c * 8);
            cp16(sV + stage * 8192 + r * 128 + sw, vb + (size_t)(t * 64 + r) * HD + c * 8);
        }
    };

#pragma unroll
    for (int i = 0; i < 4; i++) {
        int idx = tid + i * 256;
        int r = idx >> 3, c = idx & 7;
        cp16(sQ + r * 128 + ((c ^ (r & 7)) << 4), qb + (size_t)r * HD + c * 8);
    }
    issue_kv(0, 0);
    cp_commit();
    issue_kv(1, 1);
    cp_commit();

    const float scale = __expf(__ldg(temp + h));
    const float lwh   = __ldg(lw + h);
    const float inv31 = 1.f / 31.f;
    int r0i = qbase + w * 16 + g, r1i = r0i + 8;
    float y0 = (float)(r0i >> 5) * inv31, x0 = (float)(r0i & 31) * inv31;
    float y1 = (float)(r1i >> 5) * inv31, x1 = (float)(r1i & 31) * inv31;
    float c0r = -0.5f * (y0 * y0 + x0 * x0);
    float c1r = -0.5f * (y1 * y1 + x1 * x1);

    float oacc[8][4];
#pragma unroll
    for (int j = 0; j < 8; j++)
#pragma unroll
        for (int q = 0; q < 4; q++) oacc[j][q] = 0.f;
    float mrun0 = -1e30f, mrun1 = -1e30f, l0 = 0.f, l1 = 0.f;

    uint32_t aq[4][4];

    for (int t = 0; t < ITERS; t++) {
        cp_wait<1>();
        __syncthreads();
        if (t == 0) {
#pragma unroll
            for (int ks = 0; ks < 4; ks++) {
                int c = ks * 2 + (lane >> 4);
                int r = w * 16 + (lane & 15);
                ldsm_x4(aq[ks], sQ + r * 128 + ((c ^ (r & 7)) << 4));
            }
        }
        int stage = t & 1;
        uint32_t kBase = sK + stage * 8192;
        uint32_t vBase = sV + stage * 8192;

        float sacc[8][4];
#pragma unroll
        for (int j = 0; j < 8; j++)
#pragma unroll
            for (int q = 0; q < 4; q++) sacc[j][q] = 0.f;
#pragma unroll
        for (int ks = 0; ks < 4; ks++) {
            int c = ks * 2 + (lane >> 4);
            uint32_t bk[4][4];
#pragma unroll
            for (int j = 0; j < 4; j++) {
                int r = j * 16 + (lane & 15);
                ldsm_x4(bk[j], kBase + r * 128 + ((c ^ (r & 7)) << 4));
            }
#pragma unroll
            for (int j = 0; j < 4; j++) {
                mma_bf16(sacc[2 * j],     aq[ks], bk[j][0], bk[j][2]);
                mma_bf16(sacc[2 * j + 1], aq[ks], bk[j][1], bk[j][3]);
            }
        }

        int colbase = t * 64;
        float mx0 = -1e30f, mx1 = -1e30f;
#pragma unroll
        for (int nt = 0; nt < 8; nt++) {
#pragma unroll
            for (int e = 0; e < 2; e++) {
                int m = colbase + nt * 8 + ct * 2 + e;
                float ym = (float)(m >> 5) * inv31, xm = (float)(m & 31) * inv31;
                float cm = -0.5f * (ym * ym + xm * xm);
                float s0 = sacc[nt][e]     * scale + lwh * (y0 * ym + x0 * xm + c0r + cm);
                float s1 = sacc[nt][2 + e] * scale + lwh * (y1 * ym + x1 * xm + c1r + cm);
                sacc[nt][e] = s0; sacc[nt][2 + e] = s1;
                mx0 = fmaxf(mx0, s0); mx1 = fmaxf(mx1, s1);
            }
        }
        mx0 = fmaxf(mx0, __shfl_xor_sync(0xffffffffu, mx0, 1));
        mx0 = fmaxf(mx0, __shfl_xor_sync(0xffffffffu, mx0, 2));
        mx1 = fmaxf(mx1, __shfl_xor_sync(0xffffffffu, mx1, 1));
        mx1 = fmaxf(mx1, __shfl_xor_sync(0xffffffffu, mx1, 2));
        float mn0 = fmaxf(mrun0, mx0), mn1 = fmaxf(mrun1, mx1);
        float al0 = __expf(mrun0 - mn0), al1 = __expf(mrun1 - mn1);
        mrun0 = mn0; mrun1 = mn1;
        l0 *= al0; l1 *= al1;
#pragma unroll
        for (int j = 0; j < 8; j++) {
            oacc[j][0] *= al0; oacc[j][1] *= al0;
            oacc[j][2] *= al1; oacc[j][3] *= al1;
        }
#pragma unroll
        for (int nt = 0; nt < 8; nt++) {
            float p0 = __expf(sacc[nt][0] - mn0);
            float p1 = __expf(sacc[nt][1] - mn0);
            float p2 = __expf(sacc[nt][2] - mn1);
            float p3 = __expf(sacc[nt][3] - mn1);
            l0 += p0 + p1; l1 += p2 + p3;
            sacc[nt][0] = p0; sacc[nt][1] = p1; sacc[nt][2] = p2; sacc[nt][3] = p3;
        }
        uint32_t ap[4][4];
#pragma unroll
        for (int ks = 0; ks < 4; ks++) {
            ap[ks][0] = packbf(sacc[2 * ks][0],     sacc[2 * ks][1]);
            ap[ks][1] = packbf(sacc[2 * ks][2],     sacc[2 * ks][3]);
            ap[ks][2] = packbf(sacc[2 * ks + 1][0], sacc[2 * ks + 1][1]);
            ap[ks][3] = packbf(sacc[2 * ks + 1][2], sacc[2 * ks + 1][3]);
        }

#pragma unroll
        for (int ks = 0; ks < 4; ks++) {
            int rr = ks * 16 + (lane & 15);
#pragma unroll
            for (int j = 0; j < 4; j++) {
                int c = 2 * j + (lane >> 4);
                uint32_t vf[4];
                ldsm_x4_t(vf, vBase + rr * 128 + ((c ^ (rr & 7)) << 4));
                mma_bf16(oacc[2 * j],     ap[ks], vf[0], vf[1]);
                mma_bf16(oacc[2 * j + 1], ap[ks], vf[2], vf[3]);
            }
        }

        __syncthreads();
        if (t + 2 < ITERS) issue_kv(t + 2, stage);
        cp_commit();
    }

    l0 += __shfl_xor_sync(0xffffffffu, l0, 1);
    l0 += __shfl_xor_sync(0xffffffffu, l0, 2);
    l1 += __shfl_xor_sync(0xffffffffu, l1, 1);
    l1 += __shfl_xor_sync(0xffffffffu, l1, 2);
    float inv0 = ACT_S / l0, inv1 = ACT_S / l1;
    uint8_t* o0 = attn + ((size_t)(b * SEQ + r0i)) * CH + h * HD;
    uint8_t* o1 = attn + ((size_t)(b * SEQ + r1i)) * CH + h * HD;
#pragma unroll
    for (int j = 0; j < 8; j++) {
        int col = j * 8 + ct * 2;
        *reinterpret_cast<uint16_t*>(o0 + col) =
            fp8x2(oacc[j][0] * inv0, oacc[j][1] * inv0);
        *reinterpret_cast<uint16_t*>(o1 + col) =
            fp8x2(oacc[j][2] * inv1, oacc[j][3] * inv1);
    }
}

// ---------------- fp8 GEMM: BK=128, 3-stage cp.async ---------------------------
// NT: C[M,N] = A[M,K] * B[N,K]^T, both K-major fp8 e4m3. 128x128x128 tiles,
// 256 threads (4x2 warps, 32x64 per warp). Same 128B-row swizzle as bf16 ver;
// each 16B chunk = 16 fp8 (one k32 half per ldmatrix column-half).

static constexpr int G_STAGES = 3;
static constexpr int G_ASTG = 128 * 128;     // 16 KB per stage
static constexpr int G_STG  = 2 * G_ASTG;    // A+B per stage = 32 KB
static constexpr int G_DSMEM = G_STAGES * G_STG;  // 96 KB

template <class Epi>
__global__ void __launch_bounds__(256)
gemm_nt(const uint8_t* __restrict__ A, const uint8_t* __restrict__ Bm,
        int K, Epi epi) {
    extern __shared__ __align__(128) uint8_t dynsm[];
    uint32_t sBase = (uint32_t)__cvta_generic_to_shared(dynsm);

    int rowBase = blockIdx.x * 128, colBase = blockIdx.y * 128;
    int tid = threadIdx.x, lane = tid & 31, warp = tid >> 5;
    int wm = warp >> 1, wn = warp & 1;

    float acc[2][8][4];
#pragma unroll
    for (int i = 0; i < 2; i++)
#pragma unroll
        for (int j = 0; j < 8; j++)
#pragma unroll
            for (int q = 0; q < 4; q++) acc[i][j][q] = 0.f;

    const int KT = K >> 7;     // K / 128 fp8 per tile

    auto issue = [&](int kt) {
        int stage = kt % G_STAGES;
        uint32_t a0 = sBase + stage * G_STG;
        uint32_t b0 = a0 + G_ASTG;
#pragma unroll
        for (int i = 0; i < 4; i++) {
            int idx = tid + i * 256;
            int r = idx >> 3, c = idx & 7;
            uint32_t sw = (uint32_t)((c ^ (r & 7)) << 4);
            cp16(a0 + r * 128 + sw, A + (size_t)(rowBase + r) * K + kt * 128 + c * 16);
            cp16(b0 + r * 128 + sw, Bm + (size_t)(colBase + r) * K + kt * 128 + c * 16);
        }
    };

#pragma unroll
    for (int s = 0; s < G_STAGES - 1; s++) {
        if (s < KT) issue(s);
        cp_commit();
    }

    for (int kt = 0; kt < KT; kt++) {
        cp_wait<G_STAGES - 2>();
        __syncthreads();
        int nk = kt + G_STAGES - 1;
        if (nk < KT) issue(nk);
        cp_commit();

        int stage = kt % G_STAGES;
        uint32_t aB = sBase + stage * G_STG;
        uint32_t bB = aB + G_ASTG;
#pragma unroll
        for (int kk = 0; kk < 4; kk++) {      // 4 x k32 = 128 fp8
            int c = kk * 2 + (lane >> 4);
            uint32_t afr[2][4], bfr[4][4];
#pragma unroll
            for (int mt = 0; mt < 2; mt++) {
                int r = wm * 32 + mt * 16 + (lane & 15);
                ldsm_x4(afr[mt], aB + r * 128 + ((c ^ (r & 7)) << 4));
            }
#pragma unroll
            for (int j = 0; j < 4; j++) {
                int r = wn * 64 + j * 16 + (lane & 15);
                ldsm_x4(bfr[j], bB + r * 128 + ((c ^ (r & 7)) << 4));
            }
#pragma unroll
            for (int mt = 0; mt < 2; mt++)
#pragma unroll
                for (int j = 0; j < 4; j++) {
                    mma_fp8(acc[mt][2 * j],     afr[mt], bfr[j][0], bfr[j][2]);
                    mma_fp8(acc[mt][2 * j + 1], afr[mt], bfr[j][1], bfr[j][3]);
                }
        }
    }

    int g = lane >> 2, ct = lane & 3;
#pragma unroll
    for (int mt = 0; mt < 2; mt++)
#pragma unroll
        for (int nt = 0; nt < 8; nt++) {
            int r = rowBase + wm * 32 + mt * 16 + g;
            int c = colBase + wn * 64 + nt * 8 + ct * 2;
            epi(r,     c, acc[mt][nt][0], acc[mt][nt][1]);
            epi(r + 8, c, acc[mt][nt][2], acc[mt][nt][3]);
        }
}

// ---------------- epilogues (pair interface, fold 1/256) ----------------------

struct EpiQKV {
    __nv_bfloat16 *q, *k, *v;
    DI void operator()(int r, int c, float v0, float v1) const {
        int s = c / CH;
        int rem = c - s * CH;
        int h = rem >> 6, d = rem & 63;     // d even, d+1 same head
        int b = r >> 10, n = r & 1023;
        int bh = b * NH + h;
        uint32_t pk = packbf(v0 * INV_S, v1 * INV_S);
        size_t idx = ((size_t)bh * SEQ + n) * HD + d;
        __nv_bfloat16* dst = (s == 0) ? q : (s == 1) ? k : v;
        *reinterpret_cast<uint32_t*>(dst + idx) = pk;
    }
};

struct EpiResid {
    const float* base;
    const float* bias;
    const float* ls;
    float* out;
    DI void operator()(int r, int c, float v0, float v1) const {
        size_t i = (size_t)r * CH + c;
        float2 bs = *reinterpret_cast<const float2*>(base + i);
        float2 o;
        o.x = bs.x + (v0 * INV_S + __ldg(bias + c))     * __ldg(ls + c);
        o.y = bs.y + (v1 * INV_S + __ldg(bias + c + 1)) * __ldg(ls + c + 1);
        *reinterpret_cast<float2*>(out + i) = o;
    }
};

struct EpiGelu {
    const float* bias;
    uint8_t* out;
    DI void operator()(int r, int c, float v0, float v1) const {
        float t0 = v0 * INV_S + __ldg(bias + c);
        float t1 = v1 * INV_S + __ldg(bias + c + 1);
        float g0 = 0.5f * t0 * (1.f + erff(t0 * 0.70710678118654752f));
        float g1 = 0.5f * t1 * (1.f + erff(t1 * 0.70710678118654752f));
        *reinterpret_cast<uint16_t*>(out + (size_t)r * HID + c) =
            fp8x2(g0 * ACT_S, g1 * ACT_S);
    }
};

// ---------------- launch ------------------------------------------------------

extern "C" void kernel_launch(void* const* d_in, const int* in_sizes, int n_in,
                              void* d_out, int out_size) {
    (void)in_sizes; (void)n_in; (void)out_size;
    const float* x      = (const float*)d_in[0];
    const float* w_qkv  = (const float*)d_in[1];
    const float* w_proj = (const float*)d_in[2];
    const float* b_proj = (const float*)d_in[3];
    const float* ln1_g  = (const float*)d_in[4];
    const float* ln1_b  = (const float*)d_in[5];
    const float* ln2_g  = (const float*)d_in[6];
    const float* ln2_b  = (const float*)d_in[7];
    const float* temp   = (const float*)d_in[8];
    const float* lw     = (const float*)d_in[9];
    const float* ls1    = (const float*)d_in[10];
    const float* ls2    = (const float*)d_in[11];
    const float* w1     = (const float*)d_in[12];
    const float* b1     = (const float*)d_in[13];
    const float* w2     = (const float*)d_in[14];
    const float* b2     = (const float*)d_in[15];
    float* out = (float*)d_out;

    uint8_t *p_h1, *p_h2, *p_wqkvT, *p_wprojT, *p_w1T, *p_w2T, *p_attn, *p_mid;
    __nv_bfloat16 *p_q, *p_k, *p_v;
    float* p_x1;
    cudaGetSymbolAddress((void**)&p_h1, g_h1);
    cudaGetSymbolAddress((void**)&p_h2, g_h2);
    cudaGetSymbolAddress((void**)&p_wqkvT, g_wqkvT);
    cudaGetSymbolAddress((void**)&p_wprojT, g_wprojT);
    cudaGetSymbolAddress((void**)&p_w1T, g_w1T);
    cudaGetSymbolAddress((void**)&p_w2T, g_w2T);
    cudaGetSymbolAddress((void**)&p_q, g_q);
    cudaGetSymbolAddress((void**)&p_k, g_k);
    cudaGetSymbolAddress((void**)&p_v, g_v);
    cudaGetSymbolAddress((void**)&p_attn, g_attn);
    cudaGetSymbolAddress((void**)&p_x1, g_x1);
    cudaGetSymbolAddress((void**)&p_mid, g_mid);

    static bool attr_done = false;
    if (!attr_done) {
        cudaFuncSetAttribute(gemm_nt<EpiQKV>,
                             cudaFuncAttributeMaxDynamicSharedMemorySize, G_DSMEM);
        cudaFuncSetAttribute(gemm_nt<EpiResid>,
                             cudaFuncAttributeMaxDynamicSharedMemorySize, G_DSMEM);
        cudaFuncSetAttribute(gemm_nt<EpiGelu>,
                             cudaFuncAttributeMaxDynamicSharedMemorySize, G_DSMEM);
        attr_done = true;
    }

    dim3 tb(32, 8);
    transpose_fp8<<<dim3((3 * CH) / 32, CH / 32), tb>>>(w_qkv, p_wqkvT, CH, 3 * CH);
    transpose_fp8<<<dim3(CH / 32, CH / 32), tb>>>(w_proj, p_wprojT, CH, CH);
    transpose_fp8<<<dim3(HID / 32, CH / 32), tb>>>(w1, p_w1T, CH, HID);
    transpose_fp8<<<dim3(CH / 32, HID / 32), tb>>>(w2, p_w2T, HID, CH);

    ln_kernel<<<ROWS, 256>>>(x, ln1_g, ln1_b, p_h1);

    {   // QKV: [8192,768] x [2304,768]^T  (fp8)
        EpiQKV e{p_q, p_k, p_v};
        gemm_nt<EpiQKV><<<dim3(ROWS / 128, (3 * CH) / 128), 256, G_DSMEM>>>(
            p_h1, p_wqkvT, CH, e);
    }

    flash_attn<<<dim3(SEQ / 128, BH), 256>>>(p_q, p_k, p_v, temp, lw, p_attn);

    {   // proj + residual*ls1 -> x1 (fp32)
        EpiResid e{x, b_proj, ls1, p_x1};
        gemm_nt<EpiResid><<<dim3(ROWS / 128, CH / 128), 256, G_DSMEM>>>(
            p_attn, p_wprojT, CH, e);
    }
    ln_kernel<<<ROWS, 256>>>(p_x1, ln2_g, ln2_b, p_h2);

    {   // MLP1 + gelu
        EpiGelu e{b1, p_mid};
        gemm_nt<EpiGelu><<<dim3(ROWS / 128, HID / 128), 256, G_DSMEM>>>(
            p_h2, p_w1T, CH, e);
    }
    {   // MLP2 + residual*ls2 -> out (fp32)
        EpiResid e{p_x1, b2, ls2, out};
        gemm_nt<EpiResid><<<dim3(ROWS / 128, CH / 128), 256, G_DSMEM>>>(
            p_mid, p_w2T, HID, e);
    }
}

// round 9
// speedup vs baseline: 1.1073x; 1.1073x over previous
#include <cuda_runtime.h>
#include <cuda_bf16.h>
#include <cuda_fp16.h>
#include <cstdint>
#include <math.h>

#define DI __device__ __forceinline__

static constexpr int B_DIM = 8;
static constexpr int SEQ   = 1024;
static constexpr int CH    = 768;
static constexpr int NH    = 12;
static constexpr int HD    = 64;
static constexpr int HID   = 3072;
static constexpr int ROWS  = B_DIM * SEQ;   // 8192
static constexpr int BH    = B_DIM * NH;    // 96

// ---------------- scratch: device globals (no runtime allocation) ------------
__device__ __half g_h1[ROWS * CH];                  // fp16 LN1 out
__device__ __half g_h2[ROWS * CH];                  // fp16 LN2 out
__device__ __half g_wqkvT[3 * CH * CH];             // fp16 weights [N][K]
__device__ __half g_wprojT[CH * CH];
__device__ __half g_w1T[HID * CH];
__device__ __half g_w2T[CH * HID];
__device__ __nv_bfloat16 g_q[BH * SEQ * HD];        // bf16 (flash attn inputs)
__device__ __nv_bfloat16 g_k[BH * SEQ * HD];
__device__ __nv_bfloat16 g_v[BH * SEQ * HD];
__device__ __half g_attn[ROWS * CH];                // fp16 attn out
__device__ float  g_x1[ROWS * CH];
__device__ __half g_mid[(size_t)ROWS * HID];        // fp16 gelu out

// ---------------- PTX helpers -------------------------------------------------

DI void cp16(uint32_t s, const void* g) {
    asm volatile("cp.async.cg.shared.global [%0], [%1], 16;\n" :: "r"(s), "l"(g));
}
DI void cp_commit() { asm volatile("cp.async.commit_group;\n"); }
template <int N> DI void cp_wait() { asm volatile("cp.async.wait_group %0;\n" :: "n"(N)); }

DI void ldsm_x4(uint32_t* r, uint32_t addr) {
    asm volatile("ldmatrix.sync.aligned.m8n8.x4.shared.b16 {%0,%1,%2,%3}, [%4];\n"
                 : "=r"(r[0]), "=r"(r[1]), "=r"(r[2]), "=r"(r[3]) : "r"(addr));
}
DI void ldsm_x4_t(uint32_t* r, uint32_t addr) {
    asm volatile("ldmatrix.sync.aligned.m8n8.x4.trans.shared.b16 {%0,%1,%2,%3}, [%4];\n"
                 : "=r"(r[0]), "=r"(r[1]), "=r"(r[2]), "=r"(r[3]) : "r"(addr));
}

DI void mma_bf16(float* c, const uint32_t* a, uint32_t b0, uint32_t b1) {
    asm volatile(
        "mma.sync.aligned.m16n8k16.row.col.f32.bf16.bf16.f32 "
        "{%0,%1,%2,%3}, {%4,%5,%6,%7}, {%8,%9}, {%0,%1,%2,%3};\n"
        : "+f"(c[0]), "+f"(c[1]), "+f"(c[2]), "+f"(c[3])
        : "r"(a[0]), "r"(a[1]), "r"(a[2]), "r"(a[3]), "r"(b0), "r"(b1));
}

// fp16 operands, fp16 accumulators: c[0]={row g: c0,c1}, c[1]={row g+8: c0,c1}
DI void mma_f16(uint32_t* c, const uint32_t* a, uint32_t b0, uint32_t b1) {
    asm volatile(
        "mma.sync.aligned.m16n8k16.row.col.f16.f16.f16.f16 "
        "{%0,%1}, {%2,%3,%4,%5}, {%6,%7}, {%0,%1};\n"
        : "+r"(c[0]), "+r"(c[1])
        : "r"(a[0]), "r"(a[1]), "r"(a[2]), "r"(a[3]), "r"(b0), "r"(b1));
}

DI uint32_t packbf(float lo, float hi) {
    __nv_bfloat162 t = __float22bfloat162_rn(make_float2(lo, hi));
    return *reinterpret_cast<uint32_t*>(&t);
}

// ---------------- small helper kernels ---------------------------------------

// out[n][k] = fp16(in[k][n])
__global__ void transpose_f16(const float* __restrict__ in,
                              __half* __restrict__ out, int K, int Nc) {
    __shared__ float tile[32][33];
    int kb = blockIdx.y * 32, nb = blockIdx.x * 32;
    int tx = threadIdx.x, ty = threadIdx.y;   // block (32, 8)
#pragma unroll
    for (int i = 0; i < 4; i++)
        tile[ty + i * 8][tx] = in[(size_t)(kb + ty + i * 8) * Nc + nb + tx];
    __syncthreads();
#pragma unroll
    for (int i = 0; i < 4; i++)
        out[(size_t)(nb + ty + i * 8) * K + kb + tx] =
            __float2half(tile[tx][ty + i * 8]);
}

// LayerNorm, fp32 in -> fp16 out
__global__ void ln_kernel(const float* __restrict__ x, const float* __restrict__ g,
                          const float* __restrict__ b, __half* __restrict__ out) {
    int row = blockIdx.x;
    const float* xr = x + (size_t)row * CH;
    int t = threadIdx.x;
    float v0 = xr[t], v1 = xr[t + 256], v2 = xr[t + 512];
    float s  = v0 + v1 + v2;
    float s2 = v0 * v0 + v1 * v1 + v2 * v2;
#pragma unroll
    for (int o = 16; o; o >>= 1) {
        s  += __shfl_xor_sync(0xffffffffu, s,  o);
        s2 += __shfl_xor_sync(0xffffffffu, s2, o);
    }
    __shared__ float sh[16];
    int w = t >> 5, l = t & 31;
    if (l == 0) { sh[w] = s; sh[w + 8] = s2; }
    __syncthreads();
    float ts = 0.f, ts2 = 0.f;
#pragma unroll
    for (int i = 0; i < 8; i++) { ts += sh[i]; ts2 += sh[i + 8]; }
    float mu  = ts * (1.f / CH);
    float var = ts2 * (1.f / CH) - mu * mu;
    float inv = rsqrtf(var + 1e-5f);
    __half* orow = out + (size_t)row * CH;
    orow[t]       = __float2half((v0 - mu) * inv * g[t]       + b[t]);
    orow[t + 256] = __float2half((v1 - mu) * inv * g[t + 256] + b[t + 256]);
    orow[t + 512] = __float2half((v2 - mu) * inv * g[t + 512] + b[t + 512]);
}

// ---------------- fused flash attention (bf16 math, fp16 output) -------------

__global__ void __launch_bounds__(256)
flash_attn(const __nv_bfloat16* __restrict__ Q, const __nv_bfloat16* __restrict__ K,
           const __nv_bfloat16* __restrict__ V, const float* __restrict__ temp,
           const float* __restrict__ lw, __half* __restrict__ attn) {
    constexpr int ITERS = SEQ / 64;           // 16
    __shared__ __align__(16) uint8_t smem[49152];
    uint32_t sQ = (uint32_t)__cvta_generic_to_shared(smem);
    uint32_t sK = sQ + 16384;
    uint32_t sV = sK + 16384;

    int bh = blockIdx.y;
    int b = bh / NH, h = bh % NH;
    int qbase = blockIdx.x * 128;
    const __nv_bfloat16* qb = Q + ((size_t)bh * SEQ + qbase) * HD;
    const __nv_bfloat16* kb = K + (size_t)bh * SEQ * HD;
    const __nv_bfloat16* vb = V + (size_t)bh * SEQ * HD;

    int tid = threadIdx.x, lane = tid & 31, w = tid >> 5;
    int g = lane >> 2, ct = lane & 3;

    auto issue_kv = [&](int t, int stage) {
#pragma unroll
        for (int i = 0; i < 2; i++) {
            int idx = tid + i * 256;
            int r = idx >> 3, c = idx & 7;
            uint32_t sw = (uint32_t)((c ^ (r & 7)) << 4);
            cp16(sK + stage * 8192 + r * 128 + sw, kb + (size_t)(t * 64 + r) * HD + c * 8);
            cp16(sV + stage * 8192 + r * 128 + sw, vb + (size_t)(t * 64 + r) * HD + c * 8);
        }
    };

#pragma unroll
    for (int i = 0; i < 4; i++) {
        int idx = tid + i * 256;
        int r = idx >> 3, c = idx & 7;
        cp16(sQ + r * 128 + ((c ^ (r & 7)) << 4), qb + (size_t)r * HD + c * 8);
    }
    issue_kv(0, 0);
    cp_commit();
    issue_kv(1, 1);
    cp_commit();

    const float scale = __expf(__ldg(temp + h));
    const float lwh   = __ldg(lw + h);
    const float inv31 = 1.f / 31.f;
    int r0i = qbase + w * 16 + g, r1i = r0i + 8;
    float y0 = (float)(r0i >> 5) * inv31, x0 = (float)(r0i & 31) * inv31;
    float y1 = (float)(r1i >> 5) * inv31, x1 = (float)(r1i & 31) * inv31;
    float c0r = -0.5f * (y0 * y0 + x0 * x0);
    float c1r = -0.5f * (y1 * y1 + x1 * x1);

    float oacc[8][4];
#pragma unroll
    for (int j = 0; j < 8; j++)
#pragma unroll
        for (int q = 0; q < 4; q++) oacc[j][q] = 0.f;
    float mrun0 = -1e30f, mrun1 = -1e30f, l0 = 0.f, l1 = 0.f;

    uint32_t aq[4][4];

    for (int t = 0; t < ITERS; t++) {
        cp_wait<1>();
        __syncthreads();
        if (t == 0) {
#pragma unroll
            for (int ks = 0; ks < 4; ks++) {
                int c = ks * 2 + (lane >> 4);
                int r = w * 16 + (lane & 15);
                ldsm_x4(aq[ks], sQ + r * 128 + ((c ^ (r & 7)) << 4));
            }
        }
        int stage = t & 1;
        uint32_t kBase = sK + stage * 8192;
        uint32_t vBase = sV + stage * 8192;

        float sacc[8][4];
#pragma unroll
        for (int j = 0; j < 8; j++)
#pragma unroll
            for (int q = 0; q < 4; q++) sacc[j][q] = 0.f;
#pragma unroll
        for (int ks = 0; ks < 4; ks++) {
            int c = ks * 2 + (lane >> 4);
            uint32_t bk[4][4];
#pragma unroll
            for (int j = 0; j < 4; j++) {
                int r = j * 16 + (lane & 15);
                ldsm_x4(bk[j], kBase + r * 128 + ((c ^ (r & 7)) << 4));
            }
#pragma unroll
            for (int j = 0; j < 4; j++) {
                mma_bf16(sacc[2 * j],     aq[ks], bk[j][0], bk[j][2]);
                mma_bf16(sacc[2 * j + 1], aq[ks], bk[j][1], bk[j][3]);
            }
        }

        int colbase = t * 64;
        float mx0 = -1e30f, mx1 = -1e30f;
#pragma unroll
        for (int nt = 0; nt < 8; nt++) {
#pragma unroll
            for (int e = 0; e < 2; e++) {
                int m = colbase + nt * 8 + ct * 2 + e;
                float ym = (float)(m >> 5) * inv31, xm = (float)(m & 31) * inv31;
                float cm = -0.5f * (ym * ym + xm * xm);
                float s0 = sacc[nt][e]     * scale + lwh * (y0 * ym + x0 * xm + c0r + cm);
                float s1 = sacc[nt][2 + e] * scale + lwh * (y1 * ym + x1 * xm + c1r + cm);
                sacc[nt][e] = s0; sacc[nt][2 + e] = s1;
                mx0 = fmaxf(mx0, s0); mx1 = fmaxf(mx1, s1);
            }
        }
        mx0 = fmaxf(mx0, __shfl_xor_sync(0xffffffffu, mx0, 1));
        mx0 = fmaxf(mx0, __shfl_xor_sync(0xffffffffu, mx0, 2));
        mx1 = fmaxf(mx1, __shfl_xor_sync(0xffffffffu, mx1, 1));
        mx1 = fmaxf(mx1, __shfl_xor_sync(0xffffffffu, mx1, 2));
        float mn0 = fmaxf(mrun0, mx0), mn1 = fmaxf(mrun1, mx1);
        float al0 = __expf(mrun0 - mn0), al1 = __expf(mrun1 - mn1);
        mrun0 = mn0; mrun1 = mn1;
        l0 *= al0; l1 *= al1;
#pragma unroll
        for (int j = 0; j < 8; j++) {
            oacc[j][0] *= al0; oacc[j][1] *= al0;
            oacc[j][2] *= al1; oacc[j][3] *= al1;
        }
#pragma unroll
        for (int nt = 0; nt < 8; nt++) {
            float p0 = __expf(sacc[nt][0] - mn0);
            float p1 = __expf(sacc[nt][1] - mn0);
            float p2 = __expf(sacc[nt][2] - mn1);
            float p3 = __expf(sacc[nt][3] - mn1);
            l0 += p0 + p1; l1 += p2 + p3;
            sacc[nt][0] = p0; sacc[nt][1] = p1; sacc[nt][2] = p2; sacc[nt][3] = p3;
        }
        uint32_t ap[4][4];
#pragma unroll
        for (int ks = 0; ks < 4; ks++) {
            ap[ks][0] = packbf(sacc[2 * ks][0],     sacc[2 * ks][1]);
            ap[ks][1] = packbf(sacc[2 * ks][2],     sacc[2 * ks][3]);
            ap[ks][2] = packbf(sacc[2 * ks + 1][0], sacc[2 * ks + 1][1]);
            ap[ks][3] = packbf(sacc[2 * ks + 1][2], sacc[2 * ks + 1][3]);
        }

#pragma unroll
        for (int ks = 0; ks < 4; ks++) {
            int rr = ks * 16 + (lane & 15);
#pragma unroll
            for (int j = 0; j < 4; j++) {
                int c = 2 * j + (lane >> 4);
                uint32_t vf[4];
                ldsm_x4_t(vf, vBase + rr * 128 + ((c ^ (rr & 7)) << 4));
                mma_bf16(oacc[2 * j],     ap[ks], vf[0], vf[1]);
                mma_bf16(oacc[2 * j + 1], ap[ks], vf[2], vf[3]);
            }
        }

        __syncthreads();
        if (t + 2 < ITERS) issue_kv(t + 2, stage);
        cp_commit();
    }

    l0 += __shfl_xor_sync(0xffffffffu, l0, 1);
    l0 += __shfl_xor_sync(0xffffffffu, l0, 2);
    l1 += __shfl_xor_sync(0xffffffffu, l1, 1);
    l1 += __shfl_xor_sync(0xffffffffu, l1, 2);
    float inv0 = 1.f / l0, inv1 = 1.f / l1;
    __half* o0 = attn + ((size_t)(b * SEQ + r0i)) * CH + h * HD;
    __half* o1 = attn + ((size_t)(b * SEQ + r1i)) * CH + h * HD;
#pragma unroll
    for (int j = 0; j < 8; j++) {
        int col = j * 8 + ct * 2;
        *reinterpret_cast<__half2*>(o0 + col) =
            __floats2half2_rn(oacc[j][0] * inv0, oacc[j][1] * inv0);
        *reinterpret_cast<__half2*>(o1 + col) =
            __floats2half2_rn(oacc[j][2] * inv1, oacc[j][3] * inv1);
    }
}

// ---------------- fp16 GEMM (f16 accum): BK=64, 3-stage cp.async --------------
// NT: C[M,N] = A[M,K] * B[N,K]^T, fp16 in / fp16 accum. 128x128x64 tiles,
// 256 threads (4x2 warps, 32x64/warp). Same 128B-row swizzle as before.

static constexpr int G_STAGES = 3;
static constexpr int G_ASTG = 128 * 128;     // 16 KB per stage
static constexpr int G_STG  = 2 * G_ASTG;    // A+B per stage = 32 KB
static constexpr int G_DSMEM = G_STAGES * G_STG;  // 96 KB

template <class Epi>
__global__ void __launch_bounds__(256)
gemm_nt(const __half* __restrict__ A, const __half* __restrict__ Bm,
        int K, Epi epi) {
    extern __shared__ __align__(128) uint8_t dynsm[];
    uint32_t sBase = (uint32_t)__cvta_generic_to_shared(dynsm);

    int rowBase = blockIdx.x * 128, colBase = blockIdx.y * 128;
    int tid = threadIdx.x, lane = tid & 31, warp = tid >> 5;
    int wm = warp >> 1, wn = warp & 1;

    uint32_t acc[2][8][2];     // f16x2 accumulators
#pragma unroll
    for (int i = 0; i < 2; i++)
#pragma unroll
        for (int j = 0; j < 8; j++) { acc[i][j][0] = 0u; acc[i][j][1] = 0u; }

    const int KT = K >> 6;     // K / 64

    auto issue = [&](int kt) {
        int stage = kt % G_STAGES;
        uint32_t a0 = sBase + stage * G_STG;
        uint32_t b0 = a0 + G_ASTG;
#pragma unroll
        for (int i = 0; i < 4; i++) {
            int idx = tid + i * 256;
            int r = idx >> 3, c = idx & 7;
            uint32_t sw = (uint32_t)((c ^ (r & 7)) << 4);
            cp16(a0 + r * 128 + sw, A + (size_t)(rowBase + r) * K + kt * 64 + c * 8);
            cp16(b0 + r * 128 + sw, Bm + (size_t)(colBase + r) * K + kt * 64 + c * 8);
        }
    };

#pragma unroll
    for (int s = 0; s < G_STAGES - 1; s++) {
        if (s < KT) issue(s);
        cp_commit();
    }

    for (int kt = 0; kt < KT; kt++) {
        cp_wait<G_STAGES - 2>();
        __syncthreads();
        int nk = kt + G_STAGES - 1;
        if (nk < KT) issue(nk);      // safe: stage read at kt-1, proven done by barrier
        cp_commit();

        int stage = kt % G_STAGES;
        uint32_t aB = sBase + stage * G_STG;
        uint32_t bB = aB + G_ASTG;
#pragma unroll
        for (int kk = 0; kk < 4; kk++) {
            int c = kk * 2 + (lane >> 4);
            uint32_t afr[2][4], bfr[4][4];
#pragma unroll
            for (int mt = 0; mt < 2; mt++) {
                int r = wm * 32 + mt * 16 + (lane & 15);
                ldsm_x4(afr[mt], aB + r * 128 + ((c ^ (r & 7)) << 4));
            }
#pragma unroll
            for (int j = 0; j < 4; j++) {
                int r = wn * 64 + j * 16 + (lane & 15);
                ldsm_x4(bfr[j], bB + r * 128 + ((c ^ (r & 7)) << 4));
            }
#pragma unroll
            for (int mt = 0; mt < 2; mt++)
#pragma unroll
                for (int j = 0; j < 4; j++) {
                    mma_f16(acc[mt][2 * j],     afr[mt], bfr[j][0], bfr[j][2]);
                    mma_f16(acc[mt][2 * j + 1], afr[mt], bfr[j][1], bfr[j][3]);
                }
        }
    }

    int g = lane >> 2, ct = lane & 3;
#pragma unroll
    for (int mt = 0; mt < 2; mt++)
#pragma unroll
        for (int nt = 0; nt < 8; nt++) {
            int r = rowBase + wm * 32 + mt * 16 + g;
            int c = colBase + wn * 64 + nt * 8 + ct * 2;
            __half2 lo = *reinterpret_cast<__half2*>(&acc[mt][nt][0]);
            __half2 hi = *reinterpret_cast<__half2*>(&acc[mt][nt][1]);
            epi(r,     c, __low2float(lo), __high2float(lo));
            epi(r + 8, c, __low2float(hi), __high2float(hi));
        }
}

// ---------------- epilogues (pair interface) ----------------------------------

struct EpiQKV {
    __nv_bfloat16 *q, *k, *v;
    DI void operator()(int r, int c, float v0, float v1) const {
        int s = c / CH;
        int rem = c - s * CH;
        int h = rem >> 6, d = rem & 63;     // d even; d,d+1 same head
        int b = r >> 10, n = r & 1023;
        int bh = b * NH + h;
        uint32_t pk = packbf(v0, v1);
        size_t idx = ((size_t)bh * SEQ + n) * HD + d;
        __nv_bfloat16* dst = (s == 0) ? q : (s == 1) ? k : v;
        *reinterpret_cast<uint32_t*>(dst + idx) = pk;
    }
};

struct EpiResid {
    const float* base;
    const float* bias;
    const float* ls;
    float* out;
    DI void operator()(int r, int c, float v0, float v1) const {
        size_t i = (size_t)r * CH + c;
        float2 bs = *reinterpret_cast<const float2*>(base + i);
        float2 o;
        o.x = bs.x + (v0 + __ldg(bias + c))     * __ldg(ls + c);
        o.y = bs.y + (v1 + __ldg(bias + c + 1)) * __ldg(ls + c + 1);
        *reinterpret_cast<float2*>(out + i) = o;
    }
};

struct EpiGelu {
    const float* bias;
    __half* out;
    DI void operator()(int r, int c, float v0, float v1) const {
        float t0 = v0 + __ldg(bias + c);
        float t1 = v1 + __ldg(bias + c + 1);
        float g0 = 0.5f * t0 * (1.f + erff(t0 * 0.70710678118654752f));
        float g1 = 0.5f * t1 * (1.f + erff(t1 * 0.70710678118654752f));
        *reinterpret_cast<__half2*>(out + (size_t)r * HID + c) =
            __floats2half2_rn(g0, g1);
    }
};

// ---------------- launch ------------------------------------------------------

extern "C" void kernel_launch(void* const* d_in, const int* in_sizes, int n_in,
                              void* d_out, int out_size) {
    (void)in_sizes; (void)n_in; (void)out_size;
    const float* x      = (const float*)d_in[0];
    const float* w_qkv  = (const float*)d_in[1];
    const float* w_proj = (const float*)d_in[2];
    const float* b_proj = (const float*)d_in[3];
    const float* ln1_g  = (const float*)d_in[4];
    const float* ln1_b  = (const float*)d_in[5];
    const float* ln2_g  = (const float*)d_in[6];
    const float* ln2_b  = (const float*)d_in[7];
    const float* temp   = (const float*)d_in[8];
    const float* lw     = (const float*)d_in[9];
    const float* ls1    = (const float*)d_in[10];
    const float* ls2    = (const float*)d_in[11];
    const float* w1     = (const float*)d_in[12];
    const float* b1     = (const float*)d_in[13];
    const float* w2     = (const float*)d_in[14];
    const float* b2     = (const float*)d_in[15];
    float* out = (float*)d_out;

    __half *p_h1, *p_h2, *p_wqkvT, *p_wprojT, *p_w1T, *p_w2T, *p_attn, *p_mid;
    __nv_bfloat16 *p_q, *p_k, *p_v;
    float* p_x1;
    cudaGetSymbolAddress((void**)&p_h1, g_h1);
    cudaGetSymbolAddress((void**)&p_h2, g_h2);
    cudaGetSymbolAddress((void**)&p_wqkvT, g_wqkvT);
    cudaGetSymbolAddress((void**)&p_wprojT, g_wprojT);
    cudaGetSymbolAddress((void**)&p_w1T, g_w1T);
    cudaGetSymbolAddress((void**)&p_w2T, g_w2T);
    cudaGetSymbolAddress((void**)&p_q, g_q);
    cudaGetSymbolAddress((void**)&p_k, g_k);
    cudaGetSymbolAddress((void**)&p_v, g_v);
    cudaGetSymbolAddress((void**)&p_attn, g_attn);
    cudaGetSymbolAddress((void**)&p_x1, g_x1);
    cudaGetSymbolAddress((void**)&p_mid, g_mid);

    static bool attr_done = false;
    if (!attr_done) {
        cudaFuncSetAttribute(gemm_nt<EpiQKV>,
                             cudaFuncAttributeMaxDynamicSharedMemorySize, G_DSMEM);
        cudaFuncSetAttribute(gemm_nt<EpiResid>,
                             cudaFuncAttributeMaxDynamicSharedMemorySize, G_DSMEM);
        cudaFuncSetAttribute(gemm_nt<EpiGelu>,
                             cudaFuncAttributeMaxDynamicSharedMemorySize, G_DSMEM);
        attr_done = true;
    }

    dim3 tb(32, 8);
    transpose_f16<<<dim3((3 * CH) / 32, CH / 32), tb>>>(w_qkv, p_wqkvT, CH, 3 * CH);
    transpose_f16<<<dim3(CH / 32, CH / 32), tb>>>(w_proj, p_wprojT, CH, CH);
    transpose_f16<<<dim3(HID / 32, CH / 32), tb>>>(w1, p_w1T, CH, HID);
    transpose_f16<<<dim3(CH / 32, HID / 32), tb>>>(w2, p_w2T, HID, CH);

    ln_kernel<<<ROWS, 256>>>(x, ln1_g, ln1_b, p_h1);

    {   // QKV: [8192,768] x [2304,768]^T  (fp16, f16 accum)
        EpiQKV e{p_q, p_k, p_v};
        gemm_nt<EpiQKV><<<dim3(ROWS / 128, (3 * CH) / 128), 256, G_DSMEM>>>(
            p_h1, p_wqkvT, CH, e);
    }

    flash_attn<<<dim3(SEQ / 128, BH), 256>>>(p_q, p_k, p_v, temp, lw, p_attn);

    {   // proj + residual*ls1 -> x1 (fp32)
        EpiResid e{x, b_proj, ls1, p_x1};
        gemm_nt<EpiResid><<<dim3(ROWS / 128, CH / 128), 256, G_DSMEM>>>(
            p_attn, p_wprojT, CH, e);
    }
    ln_kernel<<<ROWS, 256>>>(p_x1, ln2_g, ln2_b, p_h2);

    {   // MLP1 + gelu
        EpiGelu e{b1, p_mid};
        gemm_nt<EpiGelu><<<dim3(ROWS / 128, HID / 128), 256, G_DSMEM>>>(
            p_h2, p_w1T, CH, e);
    }
    {   // MLP2 + residual*ls2 -> out (fp32)
        EpiResid e{p_x1, b2, ls2, out};
        gemm_nt<EpiResid><<<dim3(ROWS / 128, CH / 128), 256, G_DSMEM>>>(
            p_mid, p_w2T, HID, e);
    }
}

// round 10
// speedup vs baseline: 1.1317x; 1.0220x over previous
#include <cuda_runtime.h>
#include <cuda_bf16.h>
#include <cuda_fp16.h>
#include <cstdint>
#include <math.h>

#define DI __device__ __forceinline__

static constexpr int B_DIM = 8;
static constexpr int SEQ   = 1024;
static constexpr int CH    = 768;
static constexpr int NH    = 12;
static constexpr int HD    = 64;
static constexpr int HID   = 3072;
static constexpr int ROWS  = B_DIM * SEQ;   // 8192
static constexpr int BH    = B_DIM * NH;    // 96

// ---------------- scratch: device globals (no runtime allocation) ------------
__device__ __half g_h1[ROWS * CH];                  // fp16 LN1 out
__device__ __half g_h2[ROWS * CH];                  // fp16 LN2 out
__device__ __half g_wqkvT[3 * CH * CH];             // fp16 weights [N][K]
__device__ __half g_wprojT[CH * CH];
__device__ __half g_w1T[HID * CH];
__device__ __half g_w2T[CH * HID];
__device__ __nv_bfloat16 g_q[BH * SEQ * HD];        // bf16 (flash attn inputs)
__device__ __nv_bfloat16 g_k[BH * SEQ * HD];
__device__ __nv_bfloat16 g_v[BH * SEQ * HD];
__device__ __half g_attn[ROWS * CH];                // fp16 attn out
__device__ float  g_x1[ROWS * CH];
__device__ __half g_mid[(size_t)ROWS * HID];        // fp16 gelu out

// ---------------- PTX helpers -------------------------------------------------

DI void cp16(uint32_t s, const void* g) {
    asm volatile("cp.async.cg.shared.global [%0], [%1], 16;\n" :: "r"(s), "l"(g));
}
DI void cp_commit() { asm volatile("cp.async.commit_group;\n"); }
template <int N> DI void cp_wait() { asm volatile("cp.async.wait_group %0;\n" :: "n"(N)); }

DI void ldsm_x4(uint32_t* r, uint32_t addr) {
    asm volatile("ldmatrix.sync.aligned.m8n8.x4.shared.b16 {%0,%1,%2,%3}, [%4];\n"
                 : "=r"(r[0]), "=r"(r[1]), "=r"(r[2]), "=r"(r[3]) : "r"(addr));
}
DI void ldsm_x4_t(uint32_t* r, uint32_t addr) {
    asm volatile("ldmatrix.sync.aligned.m8n8.x4.trans.shared.b16 {%0,%1,%2,%3}, [%4];\n"
                 : "=r"(r[0]), "=r"(r[1]), "=r"(r[2]), "=r"(r[3]) : "r"(addr));
}

DI void mma_bf16(float* c, const uint32_t* a, uint32_t b0, uint32_t b1) {
    asm volatile(
        "mma.sync.aligned.m16n8k16.row.col.f32.bf16.bf16.f32 "
        "{%0,%1,%2,%3}, {%4,%5,%6,%7}, {%8,%9}, {%0,%1,%2,%3};\n"
        : "+f"(c[0]), "+f"(c[1]), "+f"(c[2]), "+f"(c[3])
        : "r"(a[0]), "r"(a[1]), "r"(a[2]), "r"(a[3]), "r"(b0), "r"(b1));
}

// fp16 operands, fp16 accumulators
DI void mma_f16(uint32_t* c, const uint32_t* a, uint32_t b0, uint32_t b1) {
    asm volatile(
        "mma.sync.aligned.m16n8k16.row.col.f16.f16.f16.f16 "
        "{%0,%1}, {%2,%3,%4,%5}, {%6,%7}, {%0,%1};\n"
        : "+r"(c[0]), "+r"(c[1])
        : "r"(a[0]), "r"(a[1]), "r"(a[2]), "r"(a[3]), "r"(b0), "r"(b1));
}

DI uint32_t packbf(float lo, float hi) {
    __nv_bfloat162 t = __float22bfloat162_rn(make_float2(lo, hi));
    return *reinterpret_cast<uint32_t*>(&t);
}

// ---------------- small helper kernels ---------------------------------------

__global__ void transpose_f16(const float* __restrict__ in,
                              __half* __restrict__ out, int K, int Nc) {
    __shared__ float tile[32][33];
    int kb = blockIdx.y * 32, nb = blockIdx.x * 32;
    int tx = threadIdx.x, ty = threadIdx.y;   // block (32, 8)
#pragma unroll
    for (int i = 0; i < 4; i++)
        tile[ty + i * 8][tx] = in[(size_t)(kb + ty + i * 8) * Nc + nb + tx];
    __syncthreads();
#pragma unroll
    for (int i = 0; i < 4; i++)
        out[(size_t)(nb + ty + i * 8) * K + kb + tx] =
            __float2half(tile[tx][ty + i * 8]);
}

__global__ void ln_kernel(const float* __restrict__ x, const float* __restrict__ g,
                          const float* __restrict__ b, __half* __restrict__ out) {
    int row = blockIdx.x;
    const float* xr = x + (size_t)row * CH;
    int t = threadIdx.x;
    float v0 = xr[t], v1 = xr[t + 256], v2 = xr[t + 512];
    float s  = v0 + v1 + v2;
    float s2 = v0 * v0 + v1 * v1 + v2 * v2;
#pragma unroll
    for (int o = 16; o; o >>= 1) {
        s  += __shfl_xor_sync(0xffffffffu, s,  o);
        s2 += __shfl_xor_sync(0xffffffffu, s2, o);
    }
    __shared__ float sh[16];
    int w = t >> 5, l = t & 31;
    if (l == 0) { sh[w] = s; sh[w + 8] = s2; }
    __syncthreads();
    float ts = 0.f, ts2 = 0.f;
#pragma unroll
    for (int i = 0; i < 8; i++) { ts += sh[i]; ts2 += sh[i + 8]; }
    float mu  = ts * (1.f / CH);
    float var = ts2 * (1.f / CH) - mu * mu;
    float inv = rsqrtf(var + 1e-5f);
    __half* orow = out + (size_t)row * CH;
    orow[t]       = __float2half((v0 - mu) * inv * g[t]       + b[t]);
    orow[t + 256] = __float2half((v1 - mu) * inv * g[t + 256] + b[t + 256]);
    orow[t + 512] = __float2half((v2 - mu) * inv * g[t + 512] + b[t + 512]);
}

// ---------------- fused flash attention (bf16 math, fp16 output) -------------

__global__ void __launch_bounds__(256)
flash_attn(const __nv_bfloat16* __restrict__ Q, const __nv_bfloat16* __restrict__ K,
           const __nv_bfloat16* __restrict__ V, const float* __restrict__ temp,
           const float* __restrict__ lw, __half* __restrict__ attn) {
    constexpr int ITERS = SEQ / 64;           // 16
    __shared__ __align__(16) uint8_t smem[49152];
    uint32_t sQ = (uint32_t)__cvta_generic_to_shared(smem);
    uint32_t sK = sQ + 16384;
    uint32_t sV = sK + 16384;

    int bh = blockIdx.y;
    int b = bh / NH, h = bh % NH;
    int qbase = blockIdx.x * 128;
    const __nv_bfloat16* qb = Q + ((size_t)bh * SEQ + qbase) * HD;
    const __nv_bfloat16* kb = K + (size_t)bh * SEQ * HD;
    const __nv_bfloat16* vb = V + (size_t)bh * SEQ * HD;

    int tid = threadIdx.x, lane = tid & 31, w = tid >> 5;
    int g = lane >> 2, ct = lane & 3;

    auto issue_kv = [&](int t, int stage) {
#pragma unroll
        for (int i = 0; i < 2; i++) {
            int idx = tid + i * 256;
            int r = idx >> 3, c = idx & 7;
            uint32_t sw = (uint32_t)((c ^ (r & 7)) << 4);
            cp16(sK + stage * 8192 + r * 128 + sw, kb + (size_t)(t * 64 + r) * HD + c * 8);
            cp16(sV + stage * 8192 + r * 128 + sw, vb + (size_t)(t * 64 + r) * HD + c * 8);
        }
    };

#pragma unroll
    for (int i = 0; i < 4; i++) {
        int idx = tid + i * 256;
        int r = idx >> 3, c = idx & 7;
        cp16(sQ + r * 128 + ((c ^ (r & 7)) << 4), qb + (size_t)r * HD + c * 8);
    }
    issue_kv(0, 0);
    cp_commit();
    issue_kv(1, 1);
    cp_commit();

    const float scale = __expf(__ldg(temp + h));
    const float lwh   = __ldg(lw + h);
    const float inv31 = 1.f / 31.f;
    int r0i = qbase + w * 16 + g, r1i = r0i + 8;
    float y0 = (float)(r0i >> 5) * inv31, x0 = (float)(r0i & 31) * inv31;
    float y1 = (float)(r1i >> 5) * inv31, x1 = (float)(r1i & 31) * inv31;
    float c0r = -0.5f * (y0 * y0 + x0 * x0);
    float c1r = -0.5f * (y1 * y1 + x1 * x1);

    float oacc[8][4];
#pragma unroll
    for (int j = 0; j < 8; j++)
#pragma unroll
        for (int q = 0; q < 4; q++) oacc[j][q] = 0.f;
    float mrun0 = -1e30f, mrun1 = -1e30f, l0 = 0.f, l1 = 0.f;

    uint32_t aq[4][4];

    for (int t = 0; t < ITERS; t++) {
        cp_wait<1>();
        __syncthreads();
        if (t == 0) {
#pragma unroll
            for (int ks = 0; ks < 4; ks++) {
                int c = ks * 2 + (lane >> 4);
                int r = w * 16 + (lane & 15);
                ldsm_x4(aq[ks], sQ + r * 128 + ((c ^ (r & 7)) << 4));
            }
        }
        int stage = t & 1;
        uint32_t kBase = sK + stage * 8192;
        uint32_t vBase = sV + stage * 8192;

        float sacc[8][4];
#pragma unroll
        for (int j = 0; j < 8; j++)
#pragma unroll
            for (int q = 0; q < 4; q++) sacc[j][q] = 0.f;
#pragma unroll
        for (int ks = 0; ks < 4; ks++) {
            int c = ks * 2 + (lane >> 4);
            uint32_t bk[4][4];
#pragma unroll
            for (int j = 0; j < 4; j++) {
                int r = j * 16 + (lane & 15);
                ldsm_x4(bk[j], kBase + r * 128 + ((c ^ (r & 7)) << 4));
            }
#pragma unroll
            for (int j = 0; j < 4; j++) {
                mma_bf16(sacc[2 * j],     aq[ks], bk[j][0], bk[j][2]);
                mma_bf16(sacc[2 * j + 1], aq[ks], bk[j][1], bk[j][3]);
            }
        }

        int colbase = t * 64;
        float mx0 = -1e30f, mx1 = -1e30f;
#pragma unroll
        for (int nt = 0; nt < 8; nt++) {
#pragma unroll
            for (int e = 0; e < 2; e++) {
                int m = colbase + nt * 8 + ct * 2 + e;
                float ym = (float)(m >> 5) * inv31, xm = (float)(m & 31) * inv31;
                float cm = -0.5f * (ym * ym + xm * xm);
                float s0 = sacc[nt][e]     * scale + lwh * (y0 * ym + x0 * xm + c0r + cm);
                float s1 = sacc[nt][2 + e] * scale + lwh * (y1 * ym + x1 * xm + c1r + cm);
                sacc[nt][e] = s0; sacc[nt][2 + e] = s1;
                mx0 = fmaxf(mx0, s0); mx1 = fmaxf(mx1, s1);
            }
        }
        mx0 = fmaxf(mx0, __shfl_xor_sync(0xffffffffu, mx0, 1));
        mx0 = fmaxf(mx0, __shfl_xor_sync(0xffffffffu, mx0, 2));
        mx1 = fmaxf(mx1, __shfl_xor_sync(0xffffffffu, mx1, 1));
        mx1 = fmaxf(mx1, __shfl_xor_sync(0xffffffffu, mx1, 2));
        float mn0 = fmaxf(mrun0, mx0), mn1 = fmaxf(mrun1, mx1);
        float al0 = __expf(mrun0 - mn0), al1 = __expf(mrun1 - mn1);
        mrun0 = mn0; mrun1 = mn1;
        l0 *= al0; l1 *= al1;
#pragma unroll
        for (int j = 0; j < 8; j++) {
            oacc[j][0] *= al0; oacc[j][1] *= al0;
            oacc[j][2] *= al1; oacc[j][3] *= al1;
        }
#pragma unroll
        for (int nt = 0; nt < 8; nt++) {
            float p0 = __expf(sacc[nt][0] - mn0);
            float p1 = __expf(sacc[nt][1] - mn0);
            float p2 = __expf(sacc[nt][2] - mn1);
            float p3 = __expf(sacc[nt][3] - mn1);
            l0 += p0 + p1; l1 += p2 + p3;
            sacc[nt][0] = p0; sacc[nt][1] = p1; sacc[nt][2] = p2; sacc[nt][3] = p3;
        }
        uint32_t ap[4][4];
#pragma unroll
        for (int ks = 0; ks < 4; ks++) {
            ap[ks][0] = packbf(sacc[2 * ks][0],     sacc[2 * ks][1]);
            ap[ks][1] = packbf(sacc[2 * ks][2],     sacc[2 * ks][3]);
            ap[ks][2] = packbf(sacc[2 * ks + 1][0], sacc[2 * ks + 1][1]);
            ap[ks][3] = packbf(sacc[2 * ks + 1][2], sacc[2 * ks + 1][3]);
        }

#pragma unroll
        for (int ks = 0; ks < 4; ks++) {
            int rr = ks * 16 + (lane & 15);
#pragma unroll
            for (int j = 0; j < 4; j++) {
                int c = 2 * j + (lane >> 4);
                uint32_t vf[4];
                ldsm_x4_t(vf, vBase + rr * 128 + ((c ^ (rr & 7)) << 4));
                mma_bf16(oacc[2 * j],     ap[ks], vf[0], vf[1]);
                mma_bf16(oacc[2 * j + 1], ap[ks], vf[2], vf[3]);
            }
        }

        __syncthreads();
        if (t + 2 < ITERS) issue_kv(t + 2, stage);
        cp_commit();
    }

    l0 += __shfl_xor_sync(0xffffffffu, l0, 1);
    l0 += __shfl_xor_sync(0xffffffffu, l0, 2);
    l1 += __shfl_xor_sync(0xffffffffu, l1, 1);
    l1 += __shfl_xor_sync(0xffffffffu, l1, 2);
    float inv0 = 1.f / l0, inv1 = 1.f / l1;
    __half* o0 = attn + ((size_t)(b * SEQ + r0i)) * CH + h * HD;
    __half* o1 = attn + ((size_t)(b * SEQ + r1i)) * CH + h * HD;
#pragma unroll
    for (int j = 0; j < 8; j++) {
        int col = j * 8 + ct * 2;
        *reinterpret_cast<__half2*>(o0 + col) =
            __floats2half2_rn(oacc[j][0] * inv0, oacc[j][1] * inv0);
        *reinterpret_cast<__half2*>(o1 + col) =
            __floats2half2_rn(oacc[j][2] * inv1, oacc[j][3] * inv1);
    }
}

// ---------------- fp16 GEMM (f16 accum): BK=64, 3-stage, 2 CTAs/SM ------------
// NT: C[M,N] = A[M,K] * B[N,K]^T, fp16 in / fp16 accum. 128x128x64 tiles,
// 256 threads (4x2 warps, 32x64/warp). __launch_bounds__(256,2): with the
// tensor pipe now ~50% utilized (f16 accum), a co-resident CTA fills the
// cp_wait/barrier/epilogue bubbles. 2 x 96KB smem = 192KB <= 228KB.

static constexpr int G_STAGES = 3;
static constexpr int G_ASTG = 128 * 128;     // 16 KB per stage
static constexpr int G_STG  = 2 * G_ASTG;    // A+B per stage = 32 KB
static constexpr int G_DSMEM = G_STAGES * G_STG;  // 96 KB

template <class Epi>
__global__ void __launch_bounds__(256, 2)
gemm_nt(const __half* __restrict__ A, const __half* __restrict__ Bm,
        int K, Epi epi) {
    extern __shared__ __align__(128) uint8_t dynsm[];
    uint32_t sBase = (uint32_t)__cvta_generic_to_shared(dynsm);

    int rowBase = blockIdx.x * 128, colBase = blockIdx.y * 128;
    int tid = threadIdx.x, lane = tid & 31, warp = tid >> 5;
    int wm = warp >> 1, wn = warp & 1;

    uint32_t acc[2][8][2];     // f16x2 accumulators
#pragma unroll
    for (int i = 0; i < 2; i++)
#pragma unroll
        for (int j = 0; j < 8; j++) { acc[i][j][0] = 0u; acc[i][j][1] = 0u; }

    const int KT = K >> 6;     // K / 64

    auto issue = [&](int kt) {
        int stage = kt % G_STAGES;
        uint32_t a0 = sBase + stage * G_STG;
        uint32_t b0 = a0 + G_ASTG;
#pragma unroll
        for (int i = 0; i < 4; i++) {
            int idx = tid + i * 256;
            int r = idx >> 3, c = idx & 7;
            uint32_t sw = (uint32_t)((c ^ (r & 7)) << 4);
            cp16(a0 + r * 128 + sw, A + (size_t)(rowBase + r) * K + kt * 64 + c * 8);
            cp16(b0 + r * 128 + sw, Bm + (size_t)(colBase + r) * K + kt * 64 + c * 8);
        }
    };

#pragma unroll
    for (int s = 0; s < G_STAGES - 1; s++) {
        if (s < KT) issue(s);
        cp_commit();
    }

    for (int kt = 0; kt < KT; kt++) {
        cp_wait<G_STAGES - 2>();
        __syncthreads();
        int nk = kt + G_STAGES - 1;
        if (nk < KT) issue(nk);      // safe: stage read at kt-1, proven done by barrier
        cp_commit();

        int stage = kt % G_STAGES;
        uint32_t aB = sBase + stage * G_STG;
        uint32_t bB = aB + G_ASTG;
#pragma unroll
        for (int kk = 0; kk < 4; kk++) {
            int c = kk * 2 + (lane >> 4);
            uint32_t afr[2][4], bfr[4][4];
#pragma unroll
            for (int mt = 0; mt < 2; mt++) {
                int r = wm * 32 + mt * 16 + (lane & 15);
                ldsm_x4(afr[mt], aB + r * 128 + ((c ^ (r & 7)) << 4));
            }
#pragma unroll
            for (int j = 0; j < 4; j++) {
                int r = wn * 64 + j * 16 + (lane & 15);
                ldsm_x4(bfr[j], bB + r * 128 + ((c ^ (r & 7)) << 4));
            }
#pragma unroll
            for (int mt = 0; mt < 2; mt++)
#pragma unroll
                for (int j = 0; j < 4; j++) {
                    mma_f16(acc[mt][2 * j],     afr[mt], bfr[j][0], bfr[j][2]);
                    mma_f16(acc[mt][2 * j + 1], afr[mt], bfr[j][1], bfr[j][3]);
                }
        }
    }

    int g = lane >> 2, ct = lane & 3;
#pragma unroll
    for (int mt = 0; mt < 2; mt++)
#pragma unroll
        for (int nt = 0; nt < 8; nt++) {
            int r = rowBase + wm * 32 + mt * 16 + g;
            int c = colBase + wn * 64 + nt * 8 + ct * 2;
            __half2 lo = *reinterpret_cast<__half2*>(&acc[mt][nt][0]);
            __half2 hi = *reinterpret_cast<__half2*>(&acc[mt][nt][1]);
            epi(r,     c, __low2float(lo), __high2float(lo));
            epi(r + 8, c, __low2float(hi), __high2float(hi));
        }
}

// ---------------- epilogues (pair interface) ----------------------------------

struct EpiQKV {
    __nv_bfloat16 *q, *k, *v;
    DI void operator()(int r, int c, float v0, float v1) const {
        int s = c / CH;
        int rem = c - s * CH;
        int h = rem >> 6, d = rem & 63;     // d even; d,d+1 same head
        int b = r >> 10, n = r & 1023;
        int bh = b * NH + h;
        uint32_t pk = packbf(v0, v1);
        size_t idx = ((size_t)bh * SEQ + n) * HD + d;
        __nv_bfloat16* dst = (s == 0) ? q : (s == 1) ? k : v;
        *reinterpret_cast<uint32_t*>(dst + idx) = pk;
    }
};

struct EpiResid {
    const float* base;
    const float* bias;
    const float* ls;
    float* out;
    DI void operator()(int r, int c, float v0, float v1) const {
        size_t i = (size_t)r * CH + c;
        float2 bs = *reinterpret_cast<const float2*>(base + i);
        float2 o;
        o.x = bs.x + (v0 + __ldg(bias + c))     * __ldg(ls + c);
        o.y = bs.y + (v1 + __ldg(bias + c + 1)) * __ldg(ls + c + 1);
        *reinterpret_cast<float2*>(out + i) = o;
    }
};

struct EpiGelu {
    const float* bias;
    __half* out;
    DI void operator()(int r, int c, float v0, float v1) const {
        float t0 = v0 + __ldg(bias + c);
        float t1 = v1 + __ldg(bias + c + 1);
        float g0 = 0.5f * t0 * (1.f + erff(t0 * 0.70710678118654752f));
        float g1 = 0.5f * t1 * (1.f + erff(t1 * 0.70710678118654752f));
        *reinterpret_cast<__half2*>(out + (size_t)r * HID + c) =
            __floats2half2_rn(g0, g1);
    }
};

// ---------------- launch ------------------------------------------------------

extern "C" void kernel_launch(void* const* d_in, const int* in_sizes, int n_in,
                              void* d_out, int out_size) {
    (void)in_sizes; (void)n_in; (void)out_size;
    const float* x      = (const float*)d_in[0];
    const float* w_qkv  = (const float*)d_in[1];
    const float* w_proj = (const float*)d_in[2];
    const float* b_proj = (const float*)d_in[3];
    const float* ln1_g  = (const float*)d_in[4];
    const float* ln1_b  = (const float*)d_in[5];
    const float* ln2_g  = (const float*)d_in[6];
    const float* ln2_b  = (const float*)d_in[7];
    const float* temp   = (const float*)d_in[8];
    const float* lw     = (const float*)d_in[9];
    const float* ls1    = (const float*)d_in[10];
    const float* ls2    = (const float*)d_in[11];
    const float* w1     = (const float*)d_in[12];
    const float* b1     = (const float*)d_in[13];
    const float* w2     = (const float*)d_in[14];
    const float* b2     = (const float*)d_in[15];
    float* out = (float*)d_out;

    __half *p_h1, *p_h2, *p_wqkvT, *p_wprojT, *p_w1T, *p_w2T, *p_attn, *p_mid;
    __nv_bfloat16 *p_q, *p_k, *p_v;
    float* p_x1;
    cudaGetSymbolAddress((void**)&p_h1, g_h1);
    cudaGetSymbolAddress((void**)&p_h2, g_h2);
    cudaGetSymbolAddress((void**)&p_wqkvT, g_wqkvT);
    cudaGetSymbolAddress((void**)&p_wprojT, g_wprojT);
    cudaGetSymbolAddress((void**)&p_w1T, g_w1T);
    cudaGetSymbolAddress((void**)&p_w2T, g_w2T);
    cudaGetSymbolAddress((void**)&p_q, g_q);
    cudaGetSymbolAddress((void**)&p_k, g_k);
    cudaGetSymbolAddress((void**)&p_v, g_v);
    cudaGetSymbolAddress((void**)&p_attn, g_attn);
    cudaGetSymbolAddress((void**)&p_x1, g_x1);
    cudaGetSymbolAddress((void**)&p_mid, g_mid);

    static bool attr_done = false;
    if (!attr_done) {
        cudaFuncSetAttribute(gemm_nt<EpiQKV>,
                             cudaFuncAttributeMaxDynamicSharedMemorySize, G_DSMEM);
        cudaFuncSetAttribute(gemm_nt<EpiResid>,
                             cudaFuncAttributeMaxDynamicSharedMemorySize, G_DSMEM);
        cudaFuncSetAttribute(gemm_nt<EpiGelu>,
                             cudaFuncAttributeMaxDynamicSharedMemorySize, G_DSMEM);
        attr_done = true;
    }

    dim3 tb(32, 8);
    transpose_f16<<<dim3((3 * CH) / 32, CH / 32), tb>>>(w_qkv, p_wqkvT, CH, 3 * CH);
    transpose_f16<<<dim3(CH / 32, CH / 32), tb>>>(w_proj, p_wprojT, CH, CH);
    transpose_f16<<<dim3(HID / 32, CH / 32), tb>>>(w1, p_w1T, CH, HID);
    transpose_f16<<<dim3(CH / 32, HID / 32), tb>>>(w2, p_w2T, HID, CH);

    ln_kernel<<<ROWS, 256>>>(x, ln1_g, ln1_b, p_h1);

    {   // QKV: [8192,768] x [2304,768]^T  (fp16, f16 accum)
        EpiQKV e{p_q, p_k, p_v};
        gemm_nt<EpiQKV><<<dim3(ROWS / 128, (3 * CH) / 128), 256, G_DSMEM>>>(
            p_h1, p_wqkvT, CH, e);
    }

    flash_attn<<<dim3(SEQ / 128, BH), 256>>>(p_q, p_k, p_v, temp, lw, p_attn);

    {   // proj + residual*ls1 -> x1 (fp32)
        EpiResid e{x, b_proj, ls1, p_x1};
        gemm_nt<EpiResid><<<dim3(ROWS / 128, CH / 128), 256, G_DSMEM>>>(
            p_attn, p_wprojT, CH, e);
    }
    ln_kernel<<<ROWS, 256>>>(p_x1, ln2_g, ln2_b, p_h2);

    {   // MLP1 + gelu
        EpiGelu e{b1, p_mid};
        gemm_nt<EpiGelu><<<dim3(ROWS / 128, HID / 128), 256, G_DSMEM>>>(
            p_h2, p_w1T, CH, e);
    }
    {   // MLP2 + residual*ls2 -> out (fp32)
        EpiResid e{p_x1, b2, ls2, out};
        gemm_nt<EpiResid><<<dim3(ROWS / 128, CH / 128), 256, G_DSMEM>>>(
            p_mid, p_w2T, HID, e);
    }
}